// round 1
// baseline (speedup 1.0000x reference)
#include <cuda_runtime.h>
#include <math.h>

#define BB 32
#define CC 3
#define HH 512
#define WW 512
#define HW (HH * WW)
#define PI_F 3.14159f

// Scratch (no allocations allowed): per-batch inverse homographies, light
// params, and the batch-invariant moire field (3 MB, L2-resident, reused 32x).
__device__ float g_minv[BB][9];
__device__ float g_maxlen;
__device__ float g_moire[CC * HW];

// ---------------------------------------------------------------------------
// Setup: solve the 4-point DLT (8x8, double, partial pivoting) per batch,
// invert via adjugate (scale-free), normalize. Thread 0 also computes max_len.
// ---------------------------------------------------------------------------
__global__ void setup_kernel(const float* __restrict__ dst_offsets,
                             const int* __restrict__ light_xy) {
    int b = threadIdx.x;
    if (b == 0) {
        float xf = (float)light_xy[0];
        float yf = (float)light_xy[1];
        const float S = 512.0f;
        float d0 = sqrtf(xf * xf + yf * yf);
        float d1 = sqrtf((xf - S) * (xf - S) + yf * yf);
        float d2 = sqrtf(xf * xf + (yf - S) * (yf - S));
        float d3 = sqrtf((xf - S) * (xf - S) + (yf - S) * (yf - S));
        g_maxlen = fmaxf(fmaxf(d0, d1), fmaxf(d2, d3)) * 0.5f;
    }
    if (b >= BB) return;

    const double sx[4] = {0.0, 0.0, 512.0, 512.0};
    const double sy[4] = {0.0, 512.0, 0.0, 512.0};

    double A[8][9];
    for (int k = 0; k < 4; k++) {
        double x = sx[k], y = sy[k];
        double u = x + (double)dst_offsets[(b * 4 + k) * 2 + 0];
        double v = y + (double)dst_offsets[(b * 4 + k) * 2 + 1];
        double* r0 = A[k];
        double* r1 = A[k + 4];
        r0[0] = x; r0[1] = y; r0[2] = 1.0; r0[3] = 0.0; r0[4] = 0.0; r0[5] = 0.0;
        r0[6] = -u * x; r0[7] = -u * y; r0[8] = u;
        r1[0] = 0.0; r1[1] = 0.0; r1[2] = 0.0; r1[3] = x; r1[4] = y; r1[5] = 1.0;
        r1[6] = -v * x; r1[7] = -v * y; r1[8] = v;
    }

    // Gaussian elimination with partial pivoting.
    for (int col = 0; col < 8; col++) {
        int piv = col;
        double best = fabs(A[col][col]);
        for (int r = col + 1; r < 8; r++) {
            double a = fabs(A[r][col]);
            if (a > best) { best = a; piv = r; }
        }
        if (piv != col) {
            for (int c = col; c < 9; c++) {
                double t = A[col][c]; A[col][c] = A[piv][c]; A[piv][c] = t;
            }
        }
        double inv = 1.0 / A[col][col];
        for (int r = col + 1; r < 8; r++) {
            double f = A[r][col] * inv;
            for (int c = col; c < 9; c++) A[r][c] -= f * A[col][c];
        }
    }
    double h[9];
    for (int r = 7; r >= 0; r--) {
        double s = A[r][8];
        for (int c = r + 1; c < 8; c++) s -= A[r][c] * h[c];
        h[r] = s / A[r][r];
    }
    h[8] = 1.0;

    // Adjugate inverse (scale cancels in the perspective divide).
    double m0 = h[0], m1 = h[1], m2 = h[2], m3 = h[3], m4 = h[4],
           m5 = h[5], m6 = h[6], m7 = h[7], m8 = h[8];
    double inv9[9] = {
        m4 * m8 - m5 * m7, m2 * m7 - m1 * m8, m1 * m5 - m2 * m4,
        m5 * m6 - m3 * m8, m0 * m8 - m2 * m6, m2 * m3 - m0 * m5,
        m3 * m7 - m4 * m6, m1 * m6 - m0 * m7, m0 * m4 - m1 * m3};
    double nrm = inv9[8];
    for (int k = 0; k < 9; k++) g_minv[b][k] = (float)(inv9[k] / nrm);
}

// ---------------------------------------------------------------------------
// Moire field: depends only on (channel, i, j) — computed once, reused by all
// 32 batch images from L2.
// ---------------------------------------------------------------------------
__global__ void moire_kernel(const float* __restrict__ theta,
                             const float* __restrict__ center) {
    int idx = blockIdx.x * blockDim.x + threadIdx.x;
    if (idx >= CC * HW) return;
    int c = idx / HW;
    int rem = idx - c * HW;
    int i = rem >> 9;      // row
    int j = rem & (WW - 1);  // col

    float dx = (float)i - center[c * 2 + 0];
    float dy = (float)j - center[c * 2 + 1];
    float z1 = 0.5f + 0.5f * cosf(2.0f * PI_F * sqrtf(dx * dx + dy * dy));
    float th = theta[c] / 180.0f * PI_F;
    float z2 = 0.5f + 0.5f * cosf(cosf(th) * (float)j + sinf(th) * (float)i);
    g_moire[idx] = fminf(z1, z2) * 2.0f - 1.0f;
}

// ---------------------------------------------------------------------------
// Fused warp + color + saturation + light + moire + noise.
// One thread = one pixel, all 3 channels (amortizes projective divide etc.).
// ---------------------------------------------------------------------------
__global__ void main_kernel(const float* __restrict__ imgs,
                            const float* __restrict__ noise,
                            const float* __restrict__ hue_shift,
                            const float* __restrict__ bright,
                            const float* __restrict__ contrast,
                            const int* __restrict__ light_xy,
                            float* __restrict__ out) {
    int p = blockIdx.x * blockDim.x + threadIdx.x;  // pixel in image
    if (p >= HW) return;
    int b = blockIdx.y;
    int i = p >> 9;          // row (ii)
    int j = p & (WW - 1);    // col (jj)

    const float* mv = g_minv[b];
    float x = (float)j, y = (float)i;
    float wq = mv[6] * x + mv[7] * y + mv[8];
    float invw = 1.0f / wq;
    float sxv = (mv[0] * x + mv[1] * y + mv[2]) * invw;
    float syv = (mv[3] * x + mv[4] * y + mv[5]) * invw;

    float x0f = floorf(sxv), y0f = floorf(syv);
    float wx = sxv - x0f, wy = syv - y0f;
    int x0 = (int)x0f, y0 = (int)y0f;
    int x1 = x0 + 1, y1 = y0 + 1;
    bool vx0 = (x0 >= 0) && (x0 < WW);
    bool vx1 = (x1 >= 0) && (x1 < WW);
    bool vy0 = (y0 >= 0) && (y0 < HH);
    bool vy1 = (y1 >= 0) && (y1 < HH);
    int cx0 = min(max(x0, 0), WW - 1), cx1 = min(max(x1, 0), WW - 1);
    int cy0 = min(max(y0, 0), HH - 1), cy1 = min(max(y1, 0), HH - 1);

    float ct = contrast[b];
    float br = bright[b];

    const float* imb = imgs + (size_t)b * CC * HW;
    float v[3];
#pragma unroll
    for (int c = 0; c < 3; c++) {
        const float* im = imb + c * HW;
        float v00 = (vy0 && vx0) ? im[cy0 * WW + cx0] : 0.0f;
        float v01 = (vy0 && vx1) ? im[cy0 * WW + cx1] : 0.0f;
        float v10 = (vy1 && vx0) ? im[cy1 * WW + cx0] : 0.0f;
        float v11 = (vy1 && vx1) ? im[cy1 * WW + cx1] : 0.0f;
        float val = (1.0f - wy) * ((1.0f - wx) * v00 + wx * v01) +
                    wy * ((1.0f - wx) * v10 + wx * v11);
        float o = val * ct + hue_shift[b * 3 + c] + br;
        v[c] = fminf(fmaxf(o, -1.0f), 1.0f);
    }

    // lum = mean over channels of out * [0.3, 0.6, 0.1]
    float lum = (0.3f * v[0] + 0.6f * v[1] + 0.1f * v[2]) * (1.0f / 3.0f);

    // light spot
    float xf = (float)light_xy[0];
    float yf = (float)light_xy[1];
    float di = (float)i - xf;
    float dj = (float)j - yf;
    float dl = sqrtf(di * di + dj * dj);
    float ml = g_maxlen;
    float light = (dl < ml) ? (1.0f - dl / ml) : 0.0f;

    const float kn = 0.031622776601683794f;  // sqrt(0.001)
    size_t base = (size_t)b * CC * HW + p;
#pragma unroll
    for (int c = 0; c < 3; c++) {
        float o = 0.7f * v[c] + 0.3f * lum;
        o = o + light;
        o = o + g_moire[c * HW + p] * 0.2f;
        o = o + kn * noise[base + (size_t)c * HW];
        out[base + (size_t)c * HW] = o;
    }
}

// ---------------------------------------------------------------------------
// Inputs (metadata order): 0 imgs, 1 cover, 2 dst_offsets, 3 hue_shift,
// 4 bright, 5 contrast, 6 light_xy(int32), 7 moire_theta, 8 moire_center,
// 9 noise. Output: [noised | cover], 2 * 32*3*512*512 floats.
// ---------------------------------------------------------------------------
extern "C" void kernel_launch(void* const* d_in, const int* in_sizes, int n_in,
                              void* d_out, int out_size) {
    const float* imgs        = (const float*)d_in[0];
    const float* cover       = (const float*)d_in[1];
    const float* dst_offsets = (const float*)d_in[2];
    const float* hue_shift   = (const float*)d_in[3];
    const float* bright      = (const float*)d_in[4];
    const float* contrast    = (const float*)d_in[5];
    const int*   light_xy    = (const int*)d_in[6];
    const float* moire_theta = (const float*)d_in[7];
    const float* moire_cent  = (const float*)d_in[8];
    const float* noise       = (const float*)d_in[9];
    float* out = (float*)d_out;

    const size_t n_img = (size_t)BB * CC * HW;  // 25,165,824

    setup_kernel<<<1, 32>>>(dst_offsets, light_xy);
    moire_kernel<<<(CC * HW + 255) / 256, 256>>>(moire_theta, moire_cent);

    dim3 grid(HW / 256, BB);
    main_kernel<<<grid, 256>>>(imgs, noise, hue_shift, bright, contrast,
                               light_xy, out);

    // cover pass-through: second half of output, pure bandwidth.
    cudaMemcpyAsync(out + n_img, cover, n_img * sizeof(float),
                    cudaMemcpyDeviceToDevice);
}

// round 3
// speedup vs baseline: 1.1975x; 1.1975x over previous
#include <cuda_runtime.h>
#include <math.h>

#define BB 32
#define CC 3
#define HH 512
#define WW 512
#define HW (HH * WW)
#define PI_F 3.14159f

// Scratch (no allocations allowed): per-batch inverse homographies, light
// params, and the batch-invariant moire field (3 MB, L2-resident, reused 32x).
__device__ float g_minv[BB][9];
__device__ float g_maxlen;
__device__ float g_moire[CC * HW];

// ---------------------------------------------------------------------------
// Prep kernel: every thread computes one moire element. Additionally, block 0
// threads 0..31 each compute one batch's inverse homography via the Heckbert
// closed form (unit square -> quad), and thread 32 computes max_len.
// The homography is unique up to scale; we only use Minv through a perspective
// divide, so the adjugate (un-normalized inverse) is sufficient.
// ---------------------------------------------------------------------------
__global__ void prep_kernel(const float* __restrict__ theta,
                            const float* __restrict__ center,
                            const float* __restrict__ dst_offsets,
                            const int* __restrict__ light_xy) {
    if (blockIdx.x == 0) {
        int b = threadIdx.x;
        if (b == 32) {
            float xf = (float)light_xy[0];
            float yf = (float)light_xy[1];
            const float S = 512.0f;
            float d0 = sqrtf(xf * xf + yf * yf);
            float d1 = sqrtf((xf - S) * (xf - S) + yf * yf);
            float d2 = sqrtf(xf * xf + (yf - S) * (yf - S));
            float d3 = sqrtf((xf - S) * (xf - S) + (yf - S) * (yf - S));
            g_maxlen = fmaxf(fmaxf(d0, d1), fmaxf(d2, d3)) * 0.5f;
        }
        if (b < BB) {
            const double S = 512.0;
            // src corners (x,y): k=0:(0,0) k=1:(0,S) k=2:(S,0) k=3:(S,S)
            // dst_k = src_k + offset_k
            const double sxc[4] = {0.0, 0.0, 512.0, 512.0};
            const double syc[4] = {0.0, 512.0, 0.0, 512.0};
            double du[4], dv[4];
            for (int k = 0; k < 4; k++) {
                du[k] = sxc[k] + (double)dst_offsets[(b * 4 + k) * 2 + 0];
                dv[k] = syc[k] + (double)dst_offsets[(b * 4 + k) * 2 + 1];
            }
            // Unit-square param (s,t) = (x/S, y/S):
            // (0,0)->dst0  (1,0)->dst2  (1,1)->dst3  (0,1)->dst1
            double u0 = du[0], u1 = du[2], u2 = du[3], u3 = du[1];
            double v0 = dv[0], v1 = dv[2], v2 = dv[3], v3 = dv[1];
            double sx = u0 - u1 + u2 - u3;
            double sy = v0 - v1 + v2 - v3;
            double dx1 = u1 - u2, dx2 = u3 - u2;
            double dy1 = v1 - v2, dy2 = v3 - v2;
            double den = dx1 * dy2 - dy1 * dx2;
            double g = (sx * dy2 - sy * dx2) / den;
            double h = (dx1 * sy - dy1 * sx) / den;
            double a = u1 - u0 + g * u1;
            double bq = u3 - u0 + h * u3;
            double c = u0;
            double d = v1 - v0 + g * v1;
            double e = v3 - v0 + h * v3;
            double f = v0;
            // Full map in (x,y): u = (a x + b y + cS) / (g x + h y + S)
            double m0 = a,     m1 = bq,    m2 = c * S;
            double m3 = d,     m4 = e,     m5 = f * S;
            double m6 = g,     m7 = h,     m8 = S;
            // Adjugate = inverse up to scale.
            double inv9[9] = {
                m4 * m8 - m5 * m7, m2 * m7 - m1 * m8, m1 * m5 - m2 * m4,
                m5 * m6 - m3 * m8, m0 * m8 - m2 * m6, m2 * m3 - m0 * m5,
                m3 * m7 - m4 * m6, m1 * m6 - m0 * m7, m0 * m4 - m1 * m3};
            double nrm = inv9[8];
            for (int k = 0; k < 9; k++)
                g_minv[b][k] = (float)(inv9[k] / nrm);
        }
    }

    int idx = blockIdx.x * blockDim.x + threadIdx.x;
    if (idx >= CC * HW) return;
    int c = idx / HW;
    int rem = idx - c * HW;
    int i = rem >> 9;         // row
    int j = rem & (WW - 1);   // col

    float dx = (float)i - center[c * 2 + 0];
    float dy = (float)j - center[c * 2 + 1];
    float z1 = 0.5f + 0.5f * cosf(2.0f * PI_F * sqrtf(dx * dx + dy * dy));
    float th = theta[c] / 180.0f * PI_F;
    float z2 = 0.5f + 0.5f * cosf(cosf(th) * (float)j + sinf(th) * (float)i);
    g_moire[idx] = fminf(z1, z2) * 2.0f - 1.0f;
}

// ---------------------------------------------------------------------------
// Fused warp + color + saturation + light + moire + noise + cover copy.
// One thread = one pixel, all 3 channels (amortizes projective divide etc.)
// plus the 3 corresponding cover elements (pure streaming, keeps one kernel
// saturating DRAM end-to-end instead of a serialized memcpy).
// ---------------------------------------------------------------------------
__global__ void main_kernel(const float* __restrict__ imgs,
                            const float* __restrict__ noise,
                            const float* __restrict__ cover,
                            const float* __restrict__ hue_shift,
                            const float* __restrict__ bright,
                            const float* __restrict__ contrast,
                            const int* __restrict__ light_xy,
                            float* __restrict__ out) {
    int p = blockIdx.x * blockDim.x + threadIdx.x;  // pixel in image
    if (p >= HW) return;
    int b = blockIdx.y;
    int i = p >> 9;          // row (ii)
    int j = p & (WW - 1);    // col (jj)

    const size_t n_img = (size_t)BB * CC * HW;
    size_t base = (size_t)b * CC * HW + p;

    // Issue the streaming loads early: 3 cover + 3 noise elements, fully
    // coalesced and independent of the gather chain below (raises MLP).
    float cv[3], nz[3];
#pragma unroll
    for (int c = 0; c < 3; c++) {
        cv[c] = cover[base + (size_t)c * HW];
        nz[c] = noise[base + (size_t)c * HW];
    }

    const float* mv = g_minv[b];
    float x = (float)j, y = (float)i;
    float wq = mv[6] * x + mv[7] * y + mv[8];
    float invw = 1.0f / wq;
    float sxv = (mv[0] * x + mv[1] * y + mv[2]) * invw;
    float syv = (mv[3] * x + mv[4] * y + mv[5]) * invw;

    float x0f = floorf(sxv), y0f = floorf(syv);
    float wx = sxv - x0f, wy = syv - y0f;
    int x0 = (int)x0f, y0 = (int)y0f;
    int x1 = x0 + 1, y1 = y0 + 1;
    bool vx0 = (x0 >= 0) && (x0 < WW);
    bool vx1 = (x1 >= 0) && (x1 < WW);
    bool vy0 = (y0 >= 0) && (y0 < HH);
    bool vy1 = (y1 >= 0) && (y1 < HH);
    int cx0 = min(max(x0, 0), WW - 1), cx1 = min(max(x1, 0), WW - 1);
    int cy0 = min(max(y0, 0), HH - 1), cy1 = min(max(y1, 0), HH - 1);

    float ct = contrast[b];
    float br = bright[b];

    const float* imb = imgs + (size_t)b * CC * HW;
    float v[3];
#pragma unroll
    for (int c = 0; c < 3; c++) {
        const float* im = imb + c * HW;
        float v00 = (vy0 && vx0) ? im[cy0 * WW + cx0] : 0.0f;
        float v01 = (vy0 && vx1) ? im[cy0 * WW + cx1] : 0.0f;
        float v10 = (vy1 && vx0) ? im[cy1 * WW + cx0] : 0.0f;
        float v11 = (vy1 && vx1) ? im[cy1 * WW + cx1] : 0.0f;
        float val = (1.0f - wy) * ((1.0f - wx) * v00 + wx * v01) +
                    wy * ((1.0f - wx) * v10 + wx * v11);
        float o = val * ct + hue_shift[b * 3 + c] + br;
        v[c] = fminf(fmaxf(o, -1.0f), 1.0f);
    }

    // lum = mean over channels of out * [0.3, 0.6, 0.1]
    float lum = (0.3f * v[0] + 0.6f * v[1] + 0.1f * v[2]) * (1.0f / 3.0f);

    // light spot
    float xf = (float)light_xy[0];
    float yf = (float)light_xy[1];
    float di = (float)i - xf;
    float dj = (float)j - yf;
    float dl = sqrtf(di * di + dj * dj);
    float ml = g_maxlen;
    float light = (dl < ml) ? (1.0f - dl / ml) : 0.0f;

    const float kn = 0.031622776601683794f;  // sqrt(0.001)
#pragma unroll
    for (int c = 0; c < 3; c++) {
        size_t off = base + (size_t)c * HW;
        float o = 0.7f * v[c] + 0.3f * lum;
        o = o + light;
        o = o + g_moire[c * HW + p] * 0.2f;
        o = o + kn * nz[c];
        out[off] = o;
        // cover pass-through into the second half of the output
        out[n_img + off] = cv[c];
    }
}

// ---------------------------------------------------------------------------
// Inputs (metadata order): 0 imgs, 1 cover, 2 dst_offsets, 3 hue_shift,
// 4 bright, 5 contrast, 6 light_xy(int32), 7 moire_theta, 8 moire_center,
// 9 noise. Output: [noised | cover], 2 * 32*3*512*512 floats.
// ---------------------------------------------------------------------------
extern "C" void kernel_launch(void* const* d_in, const int* in_sizes, int n_in,
                              void* d_out, int out_size) {
    const float* imgs        = (const float*)d_in[0];
    const float* cover       = (const float*)d_in[1];
    const float* dst_offsets = (const float*)d_in[2];
    const float* hue_shift   = (const float*)d_in[3];
    const float* bright      = (const float*)d_in[4];
    const float* contrast    = (const float*)d_in[5];
    const int*   light_xy    = (const int*)d_in[6];
    const float* moire_theta = (const float*)d_in[7];
    const float* moire_cent  = (const float*)d_in[8];
    const float* noise       = (const float*)d_in[9];
    float* out = (float*)d_out;

    prep_kernel<<<(CC * HW + 255) / 256, 256>>>(moire_theta, moire_cent,
                                                dst_offsets, light_xy);

    dim3 grid(HW / 256, BB);
    main_kernel<<<grid, 256>>>(imgs, noise, cover, hue_shift, bright, contrast,
                               light_xy, out);
}